// round 3
// baseline (speedup 1.0000x reference)
#include <cuda_runtime.h>

#define D      1024
#define TPB    256
#define NW     (TPB / 32)
#define FACTOR 4
#define LN_EPS 1e-5f
#define NRED   35

// Reduction slot map:
//  0 Sq      1 Sqq     2 Sqww    3 Sww     4 Swb     5 Sqwb    6 Sbb
//  7+f  Sk[f]      (Σ k)
// 11+f  Skk[f]     (Σ k²)
// 15+f  Dqk[f]     (Σ q w² k)
// 19+f  Dwk[f]     (Σ w² k)
// 23+f  Dbk[f]     (Σ b w k)
// 27+f  Sv[f]      (Σ v)
// 31+f  Svv[f]     (Σ v²)

__global__ __launch_bounds__(TPB, 3)
void attn_ds_kernel(const float* __restrict__ gq,
                    const float* __restrict__ gk,
                    const float* __restrict__ gv,
                    const float* __restrict__ glw,
                    const float* __restrict__ glb,
                    float* __restrict__ gout) {
    __shared__ float sred[NW][NRED];
    __shared__ float sbc[NRED];

    const int r = blockIdx.x;
    const int t = threadIdx.x;
    const int lane = t & 31;
    const int wid  = t >> 5;
    const size_t qoff  = (size_t)r * D;
    const size_t kvoff = (size_t)r * FACTOR * D;

    // ---- Front-batched loads: 11 x LDG.128 (max MLP) ----
    const float4 qv = reinterpret_cast<const float4*>(gq + qoff)[t];
    float4 kr[FACTOR], vr[FACTOR];
    #pragma unroll
    for (int f = 0; f < FACTOR; f++)
        kr[f] = reinterpret_cast<const float4*>(gk + kvoff + (size_t)f * D)[t];
    #pragma unroll
    for (int f = 0; f < FACTOR; f++)
        vr[f] = reinterpret_cast<const float4*>(gv + kvoff + (size_t)f * D)[t];
    const float4 wv = reinterpret_cast<const float4*>(glw)[t];
    const float4 bv = reinterpret_cast<const float4*>(glb)[t];

    const float qe[4] = {qv.x, qv.y, qv.z, qv.w};
    const float we[4] = {wv.x, wv.y, wv.z, wv.w};
    const float be[4] = {bv.x, bv.y, bv.z, bv.w};

    float red[NRED];
    #pragma unroll
    for (int i = 0; i < NRED; i++) red[i] = 0.0f;

    // ---- per-thread partial sums ----
    float ww[4], qww[4], bw[4];
    #pragma unroll
    for (int i = 0; i < 4; i++) {
        const float q = qe[i], w = we[i], b = be[i];
        ww[i]  = w * w;
        qww[i] = q * ww[i];
        bw[i]  = b * w;
        red[0] += q;
        red[1] += q * q;
        red[2] += qww[i];
        red[3] += ww[i];
        red[4] += bw[i];
        red[5] += q * bw[i];
        red[6] += b * b;
    }
    #pragma unroll
    for (int f = 0; f < FACTOR; f++) {
        const float ke[4] = {kr[f].x, kr[f].y, kr[f].z, kr[f].w};
        const float ve[4] = {vr[f].x, vr[f].y, vr[f].z, vr[f].w};
        #pragma unroll
        for (int i = 0; i < 4; i++) {
            const float k = ke[i];
            red[ 7 + f] += k;
            red[11 + f] += k * k;
            red[15 + f] += qww[i] * k;
            red[19 + f] += ww[i]  * k;
            red[23 + f] += bw[i]  * k;
            const float v = ve[i];
            red[27 + f] += v;
            red[31 + f] += v * v;
        }
    }

    // ---- single fused block reduction (2 barriers total) ----
    #pragma unroll
    for (int off = 16; off; off >>= 1)
        #pragma unroll
        for (int i = 0; i < NRED; i++)
            red[i] += __shfl_xor_sync(0xffffffffu, red[i], off);
    if (lane == 0)
        #pragma unroll
        for (int i = 0; i < NRED; i++) sred[wid][i] = red[i];
    __syncthreads();
    if (t < NRED) {
        float s = 0.0f;
        #pragma unroll
        for (int w = 0; w < NW; w++) s += sred[w][t];
        sbc[t] = s;
    }
    __syncthreads();

    // ---- scalar epilogue (computed redundantly by every thread) ----
    const float inv_d = 1.0f / (float)D;
    const float muq = sbc[0] * inv_d;
    const float rsq = rsqrtf(sbc[1] * inv_d - muq * muq + LN_EPS);
    const float C1  = rsq * (sbc[2] - muq * sbc[3]) + sbc[4];
    const float C2  = rsq * (sbc[5] - muq * sbc[4]) + sbc[6];

    float acc[4] = {0.0f, 0.0f, 0.0f, 0.0f};
    float accB = 0.0f;

    #pragma unroll
    for (int f = 0; f < FACTOR; f++) {
        const float muk = sbc[7 + f] * inv_d;
        const float rsk = rsqrtf(sbc[11 + f] * inv_d - muk * muk + LN_EPS);
        const float dot = rsq * (sbc[15 + f] - muq * sbc[19 + f]) + sbc[23 + f];
        const float wf  = rsk * (dot - muk * C1) + C2;

        const float muv = sbc[27 + f] * inv_d;
        const float rsv = rsqrtf(sbc[31 + f] * inv_d - muv * muv + LN_EPS);
        const float wrs = wf * rsv;

        const float ve[4] = {vr[f].x, vr[f].y, vr[f].z, vr[f].w};
        #pragma unroll
        for (int i = 0; i < 4; i++)
            acc[i] += wrs * (ve[i] - muv);
        accB += wf;
    }

    float4 o;
    o.x = qe[0] + we[0] * acc[0] + be[0] * accB;
    o.y = qe[1] + we[1] * acc[1] + be[1] * accB;
    o.z = qe[2] + we[2] * acc[2] + be[2] * accB;
    o.w = qe[3] + we[3] * acc[3] + be[3] * accB;
    reinterpret_cast<float4*>(gout + qoff)[t] = o;
}

extern "C" void kernel_launch(void* const* d_in, const int* in_sizes, int n_in,
                              void* d_out, int out_size) {
    const float* q  = (const float*)d_in[0];
    const float* k  = (const float*)d_in[1];
    const float* v  = (const float*)d_in[2];
    const float* lw = (const float*)d_in[3];
    const float* lb = (const float*)d_in[4];
    float* out = (float*)d_out;

    const int rows = out_size / D;   // B * Sq = 8192
    attn_ds_kernel<<<rows, TPB>>>(q, k, v, lw, lb, out);
}

// round 5
// speedup vs baseline: 1.2723x; 1.2723x over previous
#include <cuda_runtime.h>
#include <cstdint>

#define D      1024
#define TPB    256
#define NW     (TPB / 32)
#define FACTOR 4
#define LN_EPS 1e-5f
#define N2     22          // max fused-reduction width

__device__ __forceinline__ uint32_t smem_u32(const void* p) {
    uint32_t a;
    asm("{ .reg .u64 t; cvta.to.shared.u64 t, %1; cvt.u32.u64 %0, t; }"
        : "=r"(a) : "l"(p));
    return a;
}

__device__ __forceinline__ void mbar_wait(uint32_t mbar, uint32_t parity) {
    uint32_t done;
    do {
        asm volatile(
            "{\n\t.reg .pred p;\n\t"
            "mbarrier.try_wait.parity.acquire.cta.shared::cta.b64 p, [%1], %2, 0x989680;\n\t"
            "selp.b32 %0, 1, 0, p;\n\t}"
            : "=r"(done) : "r"(mbar), "r"(parity) : "memory");
    } while (!done);
}

// Block reduction of the first N slots of v[]; result broadcast via sbc.
template <int N>
__device__ __forceinline__ void block_reduce(float* v,
                                             float (*sred)[N2],
                                             float* sbc) {
    const int t    = threadIdx.x;
    const int lane = t & 31;
    const int wid  = t >> 5;
    #pragma unroll
    for (int off = 16; off; off >>= 1)
        #pragma unroll
        for (int i = 0; i < N; i++)
            v[i] += __shfl_xor_sync(0xffffffffu, v[i], off);
    if (lane == 0)
        #pragma unroll
        for (int i = 0; i < N; i++) sred[wid][i] = v[i];
    __syncthreads();
    if (t < N) {
        float s = 0.0f;
        #pragma unroll
        for (int w = 0; w < NW; w++) s += sred[w][t];
        sbc[t] = s;
    }
    __syncthreads();
}

__global__ __launch_bounds__(TPB, 4)
void attn_ds_kernel(const float* __restrict__ gq,
                    const float* __restrict__ gk,
                    const float* __restrict__ gv,
                    const float* __restrict__ glw,
                    const float* __restrict__ glb,
                    float* __restrict__ gout) {
    __shared__ alignas(16) float sq[D];
    __shared__ alignas(16) float sk[FACTOR * D];
    __shared__ alignas(16) float sv[FACTOR * D];
    __shared__ float sred[NW][N2];
    __shared__ float sbc[N2];
    __shared__ alignas(8) uint64_t mbar;

    const int r = blockIdx.x;
    const int t = threadIdx.x;
    const uint32_t mb = smem_u32(&mbar);

    if (t == 0) {
        asm volatile("mbarrier.init.shared.b64 [%0], 1;" :: "r"(mb) : "memory");
        asm volatile("fence.proxy.async.shared::cta;" ::: "memory");
    }
    __syncthreads();

    if (t == 0) {
        const uint32_t total = (D + 2 * FACTOR * D) * 4;   // 36864 bytes
        asm volatile("mbarrier.arrive.expect_tx.shared.b64 _, [%0], %1;"
                     :: "r"(mb), "r"(total) : "memory");
        asm volatile("cp.async.bulk.shared::cta.global.mbarrier::complete_tx::bytes "
                     "[%0], [%1], %2, [%3];"
                     :: "r"(smem_u32(sq)), "l"(gq + (size_t)r * D),
                        "r"(D * 4u), "r"(mb) : "memory");
        asm volatile("cp.async.bulk.shared::cta.global.mbarrier::complete_tx::bytes "
                     "[%0], [%1], %2, [%3];"
                     :: "r"(smem_u32(sk)), "l"(gk + (size_t)r * FACTOR * D),
                        "r"(FACTOR * D * 4u), "r"(mb) : "memory");
        asm volatile("cp.async.bulk.shared::cta.global.mbarrier::complete_tx::bytes "
                     "[%0], [%1], %2, [%3];"
                     :: "r"(smem_u32(sv)), "l"(gv + (size_t)r * FACTOR * D),
                        "r"(FACTOR * D * 4u), "r"(mb) : "memory");
    }

    // w/b are tiny and shared by every CTA -> L2/L1-hot regular loads.
    const float4 wv = reinterpret_cast<const float4*>(glw)[t];
    const float4 bv = reinterpret_cast<const float4*>(glb)[t];
    const float we[4] = {wv.x, wv.y, wv.z, wv.w};
    const float be[4] = {bv.x, bv.y, bv.z, bv.w};

    mbar_wait(mb, 0);

    const float4 qv = reinterpret_cast<const float4*>(sq)[t];
    const float qe[4] = {qv.x, qv.y, qv.z, qv.w};

    const float inv_d = 1.0f / (float)D;

    // ---- reduction 1: q stats ----
    {
        float r2[2] = {0.0f, 0.0f};
        #pragma unroll
        for (int i = 0; i < 4; i++) { r2[i & 0] += 0.0f; }
        r2[0] = qe[0] + qe[1] + qe[2] + qe[3];
        r2[1] = qe[0]*qe[0] + qe[1]*qe[1] + qe[2]*qe[2] + qe[3]*qe[3];
        block_reduce<2>(r2, sred, sbc);
    }
    const float muq = sbc[0] * inv_d;
    const float rsq = rsqrtf(sbc[1] * inv_d - muq * muq + LN_EPS);

    // tq = qn * w ; partials of C1 = sum(tq), C2 = sum(qn*b)
    float tq[4];
    float red[N2];
    #pragma unroll
    for (int i = 0; i < N2; i++) red[i] = 0.0f;
    #pragma unroll
    for (int i = 0; i < 4; i++) {
        const float qn = (qe[i] - muq) * rsq * we[i] + be[i];
        tq[i] = qn * we[i];
        red[0] += tq[i];
        red[1] += qn * be[i];
    }

    // ---- fused accumulation over k and v (3 ops/k-elem, 2 ops/v-elem) ----
    // slots: 0 C1p, 1 C2p, 2+f Sk, 6+f Skk, 10+f Dtqk, 14+f Sv, 18+f Svv
    #pragma unroll
    for (int f = 0; f < FACTOR; f++) {
        const float4 kf = reinterpret_cast<const float4*>(sk)[f * (TPB) + t];
        const float ke[4] = {kf.x, kf.y, kf.z, kf.w};
        #pragma unroll
        for (int i = 0; i < 4; i++) {
            red[ 2 + f] += ke[i];
            red[ 6 + f] += ke[i] * ke[i];
            red[10 + f] += tq[i] * ke[i];
        }
        const float4 vf = reinterpret_cast<const float4*>(sv)[f * (TPB) + t];
        const float ve[4] = {vf.x, vf.y, vf.z, vf.w};
        #pragma unroll
        for (int i = 0; i < 4; i++) {
            red[14 + f] += ve[i];
            red[18 + f] += ve[i] * ve[i];
        }
    }

    block_reduce<N2>(red, sred, sbc);

    const float C1 = sbc[0];
    const float C2 = sbc[1];

    float acc[4] = {0.0f, 0.0f, 0.0f, 0.0f};
    float accB = 0.0f;

    #pragma unroll
    for (int f = 0; f < FACTOR; f++) {
        const float muk = sbc[2 + f] * inv_d;
        const float rsk = rsqrtf(sbc[6 + f] * inv_d - muk * muk + LN_EPS);
        const float wf  = rsk * (sbc[10 + f] - muk * C1) + C2;

        const float muv = sbc[14 + f] * inv_d;
        const float rsv = rsqrtf(sbc[18 + f] * inv_d - muv * muv + LN_EPS);
        const float wrs = wf * rsv;

        const float4 vf = reinterpret_cast<const float4*>(sv)[f * (TPB) + t];
        acc[0] += wrs * (vf.x - muv);
        acc[1] += wrs * (vf.y - muv);
        acc[2] += wrs * (vf.z - muv);
        acc[3] += wrs * (vf.w - muv);
        accB += wf;
    }

    float4 o;
    o.x = qe[0] + we[0] * acc[0] + be[0] * accB;
    o.y = qe[1] + we[1] * acc[1] + be[1] * accB;
    o.z = qe[2] + we[2] * acc[2] + be[2] * accB;
    o.w = qe[3] + we[3] * acc[3] + be[3] * accB;
    reinterpret_cast<float4*>(gout + (size_t)r * D)[t] = o;
}

extern "C" void kernel_launch(void* const* d_in, const int* in_sizes, int n_in,
                              void* d_out, int out_size) {
    const float* q  = (const float*)d_in[0];
    const float* k  = (const float*)d_in[1];
    const float* v  = (const float*)d_in[2];
    const float* lw = (const float*)d_in[3];
    const float* lb = (const float*)d_in[4];
    float* out = (float*)d_out;

    const int rows = out_size / D;   // B * Sq = 8192
    attn_ds_kernel<<<rows, TPB>>>(q, k, v, lw, lb, out);
}